// round 14
// baseline (speedup 1.0000x reference)
#include <cuda_runtime.h>

#define DD 160
#define HH 192
#define WW 160
#define DHW (DD*HH*WW)

// Collapsed coordinate chain (exact algebra of the reference):
//   second sampler: s = v*(S/(S-1)) - 0.5,  v = grid + out_flow*rf
//   first sampler unnorm: i = g*(S/2) + (S-1)/2
#define CSX (160.0f/159.0f)
#define CSY (192.0f/191.0f)
#define CSZ (160.0f/159.0f)
#define UAX 80.0f
#define UBX 79.5f
#define UAY 96.0f
#define UBY 95.5f
#define UAZ 80.0f
#define UBZ 79.5f

__device__ __forceinline__ void sample3(const float* __restrict__ v,
                                        float ix, float iy, float iz,
                                        float& o0, float& o1, float& o2) {
    o0 = 0.0f; o1 = 0.0f; o2 = 0.0f;
    // practically always fully out of bounds -> warp-uniform early-out
    if (ix <= -1.0f || ix >= (float)WW ||
        iy <= -1.0f || iy >= (float)HH ||
        iz <= -1.0f || iz >= (float)DD) return;
    float x0f = floorf(ix), y0f = floorf(iy), z0f = floorf(iz);
    int x0 = (int)x0f, y0 = (int)y0f, z0 = (int)z0f;
    float tx = ix - x0f, ty = iy - y0f, tz = iz - z0f;
    #pragma unroll
    for (int dz = 0; dz < 2; dz++) {
        int zc = z0 + dz;
        if ((unsigned)zc >= (unsigned)DD) continue;
        float wz = dz ? tz : 1.0f - tz;
        #pragma unroll
        for (int dy = 0; dy < 2; dy++) {
            int yc = y0 + dy;
            if ((unsigned)yc >= (unsigned)HH) continue;
            float wy = dy ? ty : 1.0f - ty;
            float wzy = wz * wy;
            unsigned base = ((unsigned)zc * HH + (unsigned)yc) * WW;
            #pragma unroll
            for (int dx = 0; dx < 2; dx++) {
                int xc = x0 + dx;
                if ((unsigned)xc >= (unsigned)WW) continue;
                float w = wzy * (dx ? tx : 1.0f - tx);
                unsigned off = base + (unsigned)xc;
                o0 = fmaf(w, __ldg(v + off), o0);
                o1 = fmaf(w, __ldg(v + DHW + off), o1);
                o2 = fmaf(w, __ldg(v + 2u*DHW + off), o2);
            }
        }
    }
}

// one voxel per thread; block (32,8) = 32x8 xy tile at one z
__global__ void __launch_bounds__(256, 7) st_kernel(
                          const float* __restrict__ src,
                          const float* __restrict__ flow1,
                          const float* __restrict__ flow2,
                          const float* __restrict__ rf_p,
                          float* __restrict__ out) {
    unsigned x = blockIdx.x * 32u + threadIdx.x;
    unsigned y = blockIdx.y * 8u + threadIdx.y;
    unsigned z = blockIdx.z;

    float rf = __ldg(rf_p);
    float xf = (float)x, yf = (float)y, zf = (float)z;

    unsigned idx = (z * HH + y) * WW + x;

    float f2z = __ldg(flow2 + idx);
    float f2y = __ldg(flow2 + DHW + idx);
    float f2x = __ldg(flow2 + 2u*DHW + idx);

    // grid2 = grid + flow2*rf; first sampler unnorm (collapsed)
    float ix1 = fmaf(fmaf(f2x, rf, xf), UAX, UBX);
    float iy1 = fmaf(fmaf(f2y, rf, yf), UAY, UBY);
    float iz1 = fmaf(fmaf(f2z, rf, zf), UAZ, UBZ);

    float w0, w1, w2;
    sample3(flow1, ix1, iy1, iz1, w0, w1, w2);

    // out_flow = flow1_warped + flow2
    float oz = w0 + f2z;
    float oy = w1 + f2y;
    float ox = w2 + f2x;

    // second sampler coords (collapsed)
    float sx = fmaf(fmaf(ox, rf, xf), CSX, -0.5f);
    float sy = fmaf(fmaf(oy, rf, yf), CSY, -0.5f);
    float sz = fmaf(fmaf(oz, rf, zf), CSZ, -0.5f);

    // branchless trilinear prep: clamped offsets + masked weights
    float x0f = floorf(sx), y0f = floorf(sy), z0f = floorf(sz);
    int x0 = (int)x0f, y0 = (int)y0f, z0 = (int)z0f;
    float tx = sx - x0f, ty = sy - y0f, tz = sz - z0f;

    int x0c = min(max(x0, 0), WW - 1);
    int x1c = min(max(x0 + 1, 0), WW - 1);
    int dx1 = x1c - x0c;
    float wx0 = ((unsigned)x0       < (unsigned)WW) ? (1.0f - tx) : 0.0f;
    float wx1 = ((unsigned)(x0 + 1) < (unsigned)WW) ? tx : 0.0f;

    float wy0 = ((unsigned)y0       < (unsigned)HH) ? (1.0f - ty) : 0.0f;
    float wy1 = ((unsigned)(y0 + 1) < (unsigned)HH) ? ty : 0.0f;
    float wz0 = ((unsigned)z0       < (unsigned)DD) ? (1.0f - tz) : 0.0f;
    float wz1 = ((unsigned)(z0 + 1) < (unsigned)DD) ? tz : 0.0f;

    int y0c = min(max(y0, 0), HH - 1);
    int y1c = min(max(y0 + 1, 0), HH - 1);
    int z0c = min(max(z0, 0), DD - 1);
    int z1c = min(max(z0 + 1, 0), DD - 1);

    int rz0 = z0c * (HH * WW) + x0c;
    int rz1 = z1c * (HH * WW) + x0c;
    int o00 = rz0 + y0c * WW;
    int o01 = rz0 + y1c * WW;
    int o10 = rz1 + y0c * WW;
    int o11 = rz1 + y1c * WW;

    // 8 independent gathers back-to-back
    float a00 = __ldg(src + o00);
    float b00 = __ldg(src + o00 + dx1);
    float a01 = __ldg(src + o01);
    float b01 = __ldg(src + o01 + dx1);
    float a10 = __ldg(src + o10);
    float b10 = __ldg(src + o10 + dx1);
    float a11 = __ldg(src + o11);
    float b11 = __ldg(src + o11 + dx1);

    float r00 = fmaf(a00, wx0, b00 * wx1);
    float r01 = fmaf(a01, wx0, b01 * wx1);
    float r10 = fmaf(a10, wx0, b10 * wx1);
    float r11 = fmaf(a11, wx0, b11 * wx1);

    float img = wz0 * fmaf(wy0, r00, wy1 * r01)
              + wz1 * fmaf(wy0, r10, wy1 * r11);

    // streaming stores: keep L2 for src gathers
    __stcs(out + idx,          img);
    __stcs(out + DHW + idx,    oz);
    __stcs(out + 2u*DHW + idx, oy);
    __stcs(out + 3u*DHW + idx, ox);
}

extern "C" void kernel_launch(void* const* d_in, const int* in_sizes, int n_in,
                              void* d_out, int out_size) {
    const float* src   = (const float*)d_in[0];
    const float* flow1 = (const float*)d_in[1];
    const float* flow2 = (const float*)d_in[2];
    // d_in[3] meshgrid — analytic, not loaded
    const float* rf    = (const float*)d_in[4];
    float* out = (float*)d_out;

    dim3 block(32, 8);
    dim3 grid(WW / 32, HH / 8, DD);
    st_kernel<<<grid, block>>>(src, flow1, flow2, rf, out);
}

// round 16
// speedup vs baseline: 1.0039x; 1.0039x over previous
#include <cuda_runtime.h>

#define DD 160
#define HH 192
#define WW 160
#define DHW (DD*HH*WW)

// Collapsed coordinate chain (exact algebra of the reference):
//   second sampler: s = v*(S/(S-1)) - 0.5,  v = grid + out_flow*rf
//   first sampler unnorm: i = g*(S/2) + (S-1)/2
#define CSX (160.0f/159.0f)
#define CSY (192.0f/191.0f)
#define CSZ (160.0f/159.0f)
#define UAX 80.0f
#define UBX 79.5f
#define UAY 96.0f
#define UBY 95.5f
#define UAZ 80.0f
#define UBZ 79.5f

// Branchless trilinear prep: clamped offsets + masked weights.
struct Prep {
    int   off[4];    // 4 (z,y) corner rows + x0c
    int   dx1;       // x1c - x0c (0 at border, else 1)
    float wr[4];     // (z,y) corner weights, bounds-masked
    float wx0, wx1;  // x weights, bounds-masked
};

__device__ __forceinline__ void prep_sample(float ix, float iy, float iz, Prep& p) {
    float x0f = floorf(ix), y0f = floorf(iy), z0f = floorf(iz);
    int x0 = (int)x0f, y0 = (int)y0f, z0 = (int)z0f;
    float tx = ix - x0f, ty = iy - y0f, tz = iz - z0f;

    int x0c = min(max(x0, 0), WW - 1);
    int x1c = min(max(x0 + 1, 0), WW - 1);
    p.dx1 = x1c - x0c;
    p.wx0 = ((unsigned)x0       < (unsigned)WW) ? (1.0f - tx) : 0.0f;
    p.wx1 = ((unsigned)(x0 + 1) < (unsigned)WW) ? tx : 0.0f;

    float wy0 = ((unsigned)y0       < (unsigned)HH) ? (1.0f - ty) : 0.0f;
    float wy1 = ((unsigned)(y0 + 1) < (unsigned)HH) ? ty : 0.0f;
    float wz0 = ((unsigned)z0       < (unsigned)DD) ? (1.0f - tz) : 0.0f;
    float wz1 = ((unsigned)(z0 + 1) < (unsigned)DD) ? tz : 0.0f;

    int y0c = min(max(y0, 0), HH - 1);
    int y1c = min(max(y0 + 1, 0), HH - 1);
    int z0c = min(max(z0, 0), DD - 1);
    int z1c = min(max(z0 + 1, 0), DD - 1);

    int rz0 = z0c * (HH * WW) + x0c;
    int rz1 = z1c * (HH * WW) + x0c;
    p.off[0] = rz0 + y0c * WW;
    p.off[1] = rz0 + y1c * WW;
    p.off[2] = rz1 + y0c * WW;
    p.off[3] = rz1 + y1c * WW;
    p.wr[0] = wz0 * wy0; p.wr[1] = wz0 * wy1;
    p.wr[2] = wz1 * wy0; p.wr[3] = wz1 * wy1;
}

__device__ __forceinline__ void sample3(const float* __restrict__ v,
                                        float ix, float iy, float iz,
                                        float& o0, float& o1, float& o2) {
    o0 = 0.0f; o1 = 0.0f; o2 = 0.0f;
    // practically always fully out of bounds -> warp-uniform early-out
    if (ix <= -1.0f || ix >= (float)WW ||
        iy <= -1.0f || iy >= (float)HH ||
        iz <= -1.0f || iz >= (float)DD) return;
    float x0f = floorf(ix), y0f = floorf(iy), z0f = floorf(iz);
    int x0 = (int)x0f, y0 = (int)y0f, z0 = (int)z0f;
    float tx = ix - x0f, ty = iy - y0f, tz = iz - z0f;
    #pragma unroll
    for (int dz = 0; dz < 2; dz++) {
        int zc = z0 + dz;
        if ((unsigned)zc >= (unsigned)DD) continue;
        float wz = dz ? tz : 1.0f - tz;
        #pragma unroll
        for (int dy = 0; dy < 2; dy++) {
            int yc = y0 + dy;
            if ((unsigned)yc >= (unsigned)HH) continue;
            float wy = dy ? ty : 1.0f - ty;
            float wzy = wz * wy;
            unsigned base = ((unsigned)zc * HH + (unsigned)yc) * WW;
            #pragma unroll
            for (int dx = 0; dx < 2; dx++) {
                int xc = x0 + dx;
                if ((unsigned)xc >= (unsigned)WW) continue;
                float w = wzy * (dx ? tx : 1.0f - tx);
                unsigned off = base + (unsigned)xc;
                o0 = fmaf(w, __ldg(v + off), o0);
                o1 = fmaf(w, __ldg(v + DHW + off), o1);
                o2 = fmaf(w, __ldg(v + 2u*DHW + off), o2);
            }
        }
    }
}

__device__ __forceinline__ void compute_voxel(
        const float* __restrict__ flow1, float rf,
        float xf, float yf, float zf,
        float f2z, float f2y, float f2x,
        float& oz, float& oy, float& ox, Prep& p) {
    // grid2 = grid + flow2 * rf
    float g2z = fmaf(f2z, rf, zf);
    float g2y = fmaf(f2y, rf, yf);
    float g2x = fmaf(f2x, rf, xf);

    // first sampler unnorm (collapsed)
    float ix1 = fmaf(g2x, UAX, UBX);
    float iy1 = fmaf(g2y, UAY, UBY);
    float iz1 = fmaf(g2z, UAZ, UBZ);

    float w0, w1, w2;
    sample3(flow1, ix1, iy1, iz1, w0, w1, w2);

    oz = w0 + f2z;
    oy = w1 + f2y;
    ox = w2 + f2x;

    // second sampler coords (collapsed): s = v*(S/(S-1)) - 0.5
    float vz = fmaf(oz, rf, zf);
    float vy = fmaf(oy, rf, yf);
    float vx = fmaf(ox, rf, xf);

    float sx = fmaf(vx, CSX, -0.5f);
    float sy = fmaf(vy, CSY, -0.5f);
    float sz = fmaf(vz, CSZ, -0.5f);

    prep_sample(sx, sy, sz, p);
}

// block (32,8): warp = 32 stride-1 x at one (y,z); thread handles 4 consecutive y
// min 6 blocks/SM -> reg cap 42 -> occupancy ~64% with MLP=16 kept
__global__ void __launch_bounds__(256, 6) st_kernel(
                          const float* __restrict__ src,
                          const float* __restrict__ flow1,
                          const float* __restrict__ flow2,
                          const float* __restrict__ rf_p,
                          float* __restrict__ out) {
    unsigned x  = blockIdx.x * 32u + threadIdx.x;
    unsigned z  = blockIdx.z;
    unsigned yb = blockIdx.y * 32u + threadIdx.y * 4u;

    float rf = __ldg(rf_p);
    float xf = (float)x, zf = (float)z;

    unsigned idx0 = (z * HH + yb) * WW + x;

    // front-batched flow2 loads (MLP = 12)
    float f2z[4], f2y[4], f2x[4];
    #pragma unroll
    for (int j = 0; j < 4; j++) {
        unsigned idx = idx0 + j * WW;
        f2z[j] = __ldg(flow2 + idx);
        f2y[j] = __ldg(flow2 + DHW + idx);
        f2x[j] = __ldg(flow2 + 2u*DHW + idx);
    }

    // process j in pairs: 16 gather loads in flight per pair
    #pragma unroll
    for (int jp = 0; jp < 2; jp++) {
        int j0 = jp * 2, j1 = jp * 2 + 1;
        float oz0, oy0, ox0, oz1, oy1, ox1;
        Prep p0, p1;
        compute_voxel(flow1, rf, xf, (float)(yb + j0), zf,
                      f2z[j0], f2y[j0], f2x[j0], oz0, oy0, ox0, p0);
        compute_voxel(flow1, rf, xf, (float)(yb + j1), zf,
                      f2z[j1], f2y[j1], f2x[j1], oz1, oy1, ox1, p1);

        // 16 independent gathers issued back-to-back
        float a0[4], b0[4], a1[4], b1[4];
        #pragma unroll
        for (int r = 0; r < 4; r++) {
            a0[r] = __ldg(src + p0.off[r]);
            b0[r] = __ldg(src + p0.off[r] + p0.dx1);
            a1[r] = __ldg(src + p1.off[r]);
            b1[r] = __ldg(src + p1.off[r] + p1.dx1);
        }

        float img0 = 0.0f, img1 = 0.0f;
        #pragma unroll
        for (int r = 0; r < 4; r++) {
            img0 = fmaf(p0.wr[r], fmaf(a0[r], p0.wx0, b0[r] * p0.wx1), img0);
            img1 = fmaf(p1.wr[r], fmaf(a1[r], p1.wx0, b1[r] * p1.wx1), img1);
        }

        // streaming stores: keep L2 for src gathers
        unsigned idxA = idx0 + j0 * WW;
        unsigned idxB = idx0 + j1 * WW;
        __stcs(out + idxA,            img0);
        __stcs(out + DHW + idxA,      oz0);
        __stcs(out + 2u*DHW + idxA,   oy0);
        __stcs(out + 3u*DHW + idxA,   ox0);
        __stcs(out + idxB,            img1);
        __stcs(out + DHW + idxB,      oz1);
        __stcs(out + 2u*DHW + idxB,   oy1);
        __stcs(out + 3u*DHW + idxB,   ox1);
    }
}

extern "C" void kernel_launch(void* const* d_in, const int* in_sizes, int n_in,
                              void* d_out, int out_size) {
    const float* src   = (const float*)d_in[0];
    const float* flow1 = (const float*)d_in[1];
    const float* flow2 = (const float*)d_in[2];
    // d_in[3] meshgrid — analytic, not loaded
    const float* rf    = (const float*)d_in[4];
    float* out = (float*)d_out;

    dim3 block(32, 8);
    dim3 grid(WW / 32, HH / 32, DD);
    st_kernel<<<grid, block>>>(src, flow1, flow2, rf, out);
}

// round 17
// speedup vs baseline: 1.0433x; 1.0393x over previous
#include <cuda_runtime.h>

#define DD 160
#define HH 192
#define WW 160
#define DHW (DD*HH*WW)

// Collapsed coordinate chain (exact algebra of the reference):
//   second sampler: s = v*(S/(S-1)) - 0.5,  v = grid + out_flow*rf
//   first sampler unnorm: i = g*(S/2) + (S-1)/2
#define CSX (160.0f/159.0f)
#define CSY (192.0f/191.0f)
#define CSZ (160.0f/159.0f)
#define UAX 80.0f
#define UBX 79.5f
#define UAY 96.0f
#define UBY 95.5f
#define UAZ 80.0f
#define UBZ 79.5f

// Branchless trilinear prep: clamped offsets + masked weights.
struct Prep {
    int   off[4];    // 4 (z,y) corner rows + x0c
    int   dx1;       // x1c - x0c (0 at border, else 1)
    float wr[4];     // (z,y) corner weights, bounds-masked
    float wx0, wx1;  // x weights, bounds-masked
};

__device__ __forceinline__ void prep_sample(float ix, float iy, float iz, Prep& p) {
    float x0f = floorf(ix), y0f = floorf(iy), z0f = floorf(iz);
    int x0 = (int)x0f, y0 = (int)y0f, z0 = (int)z0f;
    float tx = ix - x0f, ty = iy - y0f, tz = iz - z0f;

    int x0c = min(max(x0, 0), WW - 1);
    int x1c = min(max(x0 + 1, 0), WW - 1);
    p.dx1 = x1c - x0c;
    p.wx0 = ((unsigned)x0       < (unsigned)WW) ? (1.0f - tx) : 0.0f;
    p.wx1 = ((unsigned)(x0 + 1) < (unsigned)WW) ? tx : 0.0f;

    float wy0 = ((unsigned)y0       < (unsigned)HH) ? (1.0f - ty) : 0.0f;
    float wy1 = ((unsigned)(y0 + 1) < (unsigned)HH) ? ty : 0.0f;
    float wz0 = ((unsigned)z0       < (unsigned)DD) ? (1.0f - tz) : 0.0f;
    float wz1 = ((unsigned)(z0 + 1) < (unsigned)DD) ? tz : 0.0f;

    int y0c = min(max(y0, 0), HH - 1);
    int y1c = min(max(y0 + 1, 0), HH - 1);
    int z0c = min(max(z0, 0), DD - 1);
    int z1c = min(max(z0 + 1, 0), DD - 1);

    int rz0 = z0c * (HH * WW) + x0c;
    int rz1 = z1c * (HH * WW) + x0c;
    p.off[0] = rz0 + y0c * WW;
    p.off[1] = rz0 + y1c * WW;
    p.off[2] = rz1 + y0c * WW;
    p.off[3] = rz1 + y1c * WW;
    p.wr[0] = wz0 * wy0; p.wr[1] = wz0 * wy1;
    p.wr[2] = wz1 * wy0; p.wr[3] = wz1 * wy1;
}

__device__ __forceinline__ void sample3(const float* __restrict__ v,
                                        float ix, float iy, float iz,
                                        float& o0, float& o1, float& o2) {
    o0 = 0.0f; o1 = 0.0f; o2 = 0.0f;
    // practically always fully out of bounds -> warp-uniform early-out
    if (ix <= -1.0f || ix >= (float)WW ||
        iy <= -1.0f || iy >= (float)HH ||
        iz <= -1.0f || iz >= (float)DD) return;
    float x0f = floorf(ix), y0f = floorf(iy), z0f = floorf(iz);
    int x0 = (int)x0f, y0 = (int)y0f, z0 = (int)z0f;
    float tx = ix - x0f, ty = iy - y0f, tz = iz - z0f;
    #pragma unroll
    for (int dz = 0; dz < 2; dz++) {
        int zc = z0 + dz;
        if ((unsigned)zc >= (unsigned)DD) continue;
        float wz = dz ? tz : 1.0f - tz;
        #pragma unroll
        for (int dy = 0; dy < 2; dy++) {
            int yc = y0 + dy;
            if ((unsigned)yc >= (unsigned)HH) continue;
            float wy = dy ? ty : 1.0f - ty;
            float wzy = wz * wy;
            unsigned base = ((unsigned)zc * HH + (unsigned)yc) * WW;
            #pragma unroll
            for (int dx = 0; dx < 2; dx++) {
                int xc = x0 + dx;
                if ((unsigned)xc >= (unsigned)WW) continue;
                float w = wzy * (dx ? tx : 1.0f - tx);
                unsigned off = base + (unsigned)xc;
                o0 = fmaf(w, __ldg(v + off), o0);
                o1 = fmaf(w, __ldg(v + DHW + off), o1);
                o2 = fmaf(w, __ldg(v + 2u*DHW + off), o2);
            }
        }
    }
}

__device__ __forceinline__ void compute_voxel(
        const float* __restrict__ flow1, float rf,
        float xf, float yf, float zf,
        float f2z, float f2y, float f2x,
        float& oz, float& oy, float& ox, Prep& p) {
    // grid2 = grid + flow2 * rf
    float g2z = fmaf(f2z, rf, zf);
    float g2y = fmaf(f2y, rf, yf);
    float g2x = fmaf(f2x, rf, xf);

    // first sampler unnorm (collapsed)
    float ix1 = fmaf(g2x, UAX, UBX);
    float iy1 = fmaf(g2y, UAY, UBY);
    float iz1 = fmaf(g2z, UAZ, UBZ);

    float w0, w1, w2;
    sample3(flow1, ix1, iy1, iz1, w0, w1, w2);

    oz = w0 + f2z;
    oy = w1 + f2y;
    ox = w2 + f2x;

    // second sampler coords (collapsed): s = v*(S/(S-1)) - 0.5
    float vz = fmaf(oz, rf, zf);
    float vy = fmaf(oy, rf, yf);
    float vx = fmaf(ox, rf, xf);

    float sx = fmaf(vx, CSX, -0.5f);
    float sy = fmaf(vy, CSY, -0.5f);
    float sz = fmaf(vz, CSZ, -0.5f);

    prep_sample(sx, sy, sz, p);
}

// block (32,8): warp = 32 stride-1 x at one (y,z); thread handles 4 consecutive y
// all 4 voxels batched: 32 gather loads in flight per thread
__global__ void __launch_bounds__(256) st_kernel(
                          const float* __restrict__ src,
                          const float* __restrict__ flow1,
                          const float* __restrict__ flow2,
                          const float* __restrict__ rf_p,
                          float* __restrict__ out) {
    unsigned x  = blockIdx.x * 32u + threadIdx.x;
    unsigned z  = blockIdx.z;
    unsigned yb = blockIdx.y * 32u + threadIdx.y * 4u;

    float rf = __ldg(rf_p);
    float xf = (float)x, zf = (float)z;

    unsigned idx0 = (z * HH + yb) * WW + x;

    // front-batched flow2 loads (MLP = 12)
    float f2z[4], f2y[4], f2x[4];
    #pragma unroll
    for (int j = 0; j < 4; j++) {
        unsigned idx = idx0 + j * WW;
        f2z[j] = __ldg(flow2 + idx);
        f2y[j] = __ldg(flow2 + DHW + idx);
        f2x[j] = __ldg(flow2 + 2u*DHW + idx);
    }

    // compute all 4 voxels' prep, then 32 gathers in one burst
    float oz[4], oy[4], ox[4];
    Prep p[4];
    #pragma unroll
    for (int j = 0; j < 4; j++) {
        compute_voxel(flow1, rf, xf, (float)(yb + j), zf,
                      f2z[j], f2y[j], f2x[j], oz[j], oy[j], ox[j], p[j]);
    }

    // 32 independent gathers issued back-to-back
    float a[4][4], b[4][4];
    #pragma unroll
    for (int j = 0; j < 4; j++) {
        #pragma unroll
        for (int r = 0; r < 4; r++) {
            a[j][r] = __ldg(src + p[j].off[r]);
            b[j][r] = __ldg(src + p[j].off[r] + p[j].dx1);
        }
    }

    #pragma unroll
    for (int j = 0; j < 4; j++) {
        float img = 0.0f;
        #pragma unroll
        for (int r = 0; r < 4; r++) {
            img = fmaf(p[j].wr[r],
                       fmaf(a[j][r], p[j].wx0, b[j][r] * p[j].wx1), img);
        }
        unsigned idx = idx0 + j * WW;
        // streaming stores: keep L2 for src gathers
        __stcs(out + idx,          img);
        __stcs(out + DHW + idx,    oz[j]);
        __stcs(out + 2u*DHW + idx, oy[j]);
        __stcs(out + 3u*DHW + idx, ox[j]);
    }
}

extern "C" void kernel_launch(void* const* d_in, const int* in_sizes, int n_in,
                              void* d_out, int out_size) {
    const float* src   = (const float*)d_in[0];
    const float* flow1 = (const float*)d_in[1];
    const float* flow2 = (const float*)d_in[2];
    // d_in[3] meshgrid — analytic, not loaded
    const float* rf    = (const float*)d_in[4];
    float* out = (float*)d_out;

    dim3 block(32, 8);
    dim3 grid(WW / 32, HH / 32, DD);
    st_kernel<<<grid, block>>>(src, flow1, flow2, rf, out);
}